// round 10
// baseline (speedup 1.0000x reference)
#include <cuda_runtime.h>
#include <cuda_fp16.h>
#include <cstdint>

#define BS    32
#define EMB   512
#define GL    256
#define WFLAT 36864
#define HIN   96
#define HOUT  94
#define NPIX  9216
#define XCLAMP (32u*64u*9216u - 4u)

typedef unsigned long long u64;
typedef unsigned int u32;

__device__ __align__(16) float  g_hdn_t[GL * BS];
// B fp16 fragment order (fused kh): [s][kh(3)][ks'(12)][ntp(4)][lane(32)][ntl(2)][reg(2)][half(2)]
__device__ __align__(16) __half g_wB[BS * WFLAT];

// ---- helpers ----------------------------------------------------------------
__device__ __forceinline__ void fma2(u64& d, u64 a, u64 b) {
    asm("fma.rn.f32x2 %0, %1, %2, %0;" : "+l"(d) : "l"(a), "l"(b));
}
__device__ __forceinline__ void unpk2(u64 v, float& lo, float& hi) {
    asm("mov.b64 {%0, %1}, %2;" : "=f"(lo), "=f"(hi) : "l"(v));
}
__device__ __forceinline__ u32 smem_u32(const void* p) {
    u32 a; asm("{ .reg .u64 t; cvta.to.shared.u64 t, %1; cvt.u32.u64 %0, t; }" : "=r"(a) : "l"(p));
    return a;
}
__device__ __forceinline__ void cpa16(u32 dst, const void* src) {
    asm volatile("cp.async.cg.shared.global [%0], [%1], 16;" :: "r"(dst), "l"(src));
}
#define CPA_COMMIT() asm volatile("cp.async.commit_group;" ::: "memory")
#define CPA_WAIT(N)  asm volatile("cp.async.wait_group %0;" :: "n"(N) : "memory")

__device__ __forceinline__ void mma16(float* c, u32 a0, u32 a1, u32 a2, u32 a3,
                                      u32 b0, u32 b1) {
    asm("mma.sync.aligned.m16n8k16.row.col.f32.f16.f16.f32 "
        "{%0,%1,%2,%3}, {%4,%5,%6,%7}, {%8,%9}, {%0,%1,%2,%3};"
        : "+f"(c[0]), "+f"(c[1]), "+f"(c[2]), "+f"(c[3])
        : "r"(a0), "r"(a1), "r"(a2), "r"(a3), "r"(b0), "r"(b1));
}

// ---------------------------------------------------------------------------
// hyper1: hdn_t[j][s] = relu(emb[s,:]·w1[j,:] + b1[j])
// grid = 128 (16 sample-pairs x 8 jg), block 512 = 32 j x 16 k-slices.
// Each thread reuses its w1 fragment across 2 samples.
// ---------------------------------------------------------------------------
__global__ __launch_bounds__(512) void hyper1(const float* __restrict__ emb,
                                              const float* __restrict__ w1w,
                                              const float* __restrict__ w1b) {
    __shared__ float red[2][16][33];
    const int tid = threadIdx.x;
    const int sp = blockIdx.x >> 3, jg = blockIdx.x & 7;
    const int lane = tid & 31, slice = tid >> 5;
    const int j = jg * 32 + lane;
    const int s0 = sp * 2;
    const float4* wr = (const float4*)(w1w + (size_t)j * EMB + slice * 32);
    const float4* e0 = (const float4*)(emb + (size_t)s0 * EMB + slice * 32);
    const float4* e1 = (const float4*)(emb + (size_t)(s0 + 1) * EMB + slice * 32);
    float a0 = 0.f, a1 = 0.f;
#pragma unroll
    for (int k = 0; k < 8; k++) {
        const float4 w = wr[k];
        const float4 x0 = e0[k], x1 = e1[k];
        a0 += w.x * x0.x + w.y * x0.y + w.z * x0.z + w.w * x0.w;
        a1 += w.x * x1.x + w.y * x1.y + w.z * x1.z + w.w * x1.w;
    }
    red[0][slice][lane] = a0;
    red[1][slice][lane] = a1;
    __syncthreads();
    if (tid < 64) {
        const int si = tid >> 5, l = tid & 31;
        float a = 0.f;
#pragma unroll
        for (int t = 0; t < 16; t++) a += red[si][t][l];
        const int jj = jg * 32 + l;
        a += w1b[jj];
        g_hdn_t[jj * BS + s0 + si] = a > 0.f ? a : 0.f;
    }
}

// ---------------------------------------------------------------------------
// hyper2: weight GEMM; float4 staging; epilogue writes fp16 in fused-kh
// fragment order: ks' = kw*4 + (ic>>4), tile per kh = 12288 halves.
// ---------------------------------------------------------------------------
__global__ __launch_bounds__(128) void hyper2(const float* __restrict__ w2w,
                                              const float* __restrict__ w2b) {
    __shared__ float hdn_sm[GL * BS];
    __shared__ __align__(16) float2 w2td[64 * 33];

    const int tid = threadIdx.x;
    const int lane = tid & 31, sg = tid >> 5;
    const int r0 = blockIdx.x * 32;

#pragma unroll
    for (int it = 0; it < 16; it++)
        ((float4*)hdn_sm)[it * 128 + tid] = ((const float4*)g_hdn_t)[it * 128 + tid];

    u64 acc2[4];
#pragma unroll
    for (int i = 0; i < 4; i++) acc2[i] = 0ull;

    for (int kc = 0; kc < 4; kc++) {
        __syncthreads();
#pragma unroll
        for (int it = 0; it < 4; it++) {
            const int idx = it * 128 + tid;
            const int r = idx >> 4, c4 = idx & 15;
            const float4 v = *(const float4*)&w2w[(size_t)(r0 + r) * GL + kc * 64 + c4 * 4];
            w2td[(c4 * 4 + 0) * 33 + r] = make_float2(v.x, v.x);
            w2td[(c4 * 4 + 1) * 33 + r] = make_float2(v.y, v.y);
            w2td[(c4 * 4 + 2) * 33 + r] = make_float2(v.z, v.z);
            w2td[(c4 * 4 + 3) * 33 + r] = make_float2(v.w, v.w);
        }
        __syncthreads();
#pragma unroll
        for (int k = 0; k < 64; k++) {
            const u64 wd = *(const u64*)&w2td[k * 33 + lane];
            const float* hb = &hdn_sm[(kc * 64 + k) * BS + sg * 8];
            fma2(acc2[0], wd, *(const u64*)&hb[0]);
            fma2(acc2[1], wd, *(const u64*)&hb[2]);
            fma2(acc2[2], wd, *(const u64*)&hb[4]);
            fma2(acc2[3], wd, *(const u64*)&hb[6]);
        }
    }

    const int row = r0 + lane;          // row = oc*576 + ic*9 + kk
    const int oc  = row / 576;
    const int rem = row - oc * 576;
    const int ic  = rem / 9;
    const int kk  = rem - ic * 9;
    const int kh  = kk / 3, kw = kk - kh * 3;
    const int ksq = kw * 4 + (ic >> 4);
    const int kpos = ic & 15;
    const int reg = kpos >> 3, klo = kpos & 7;
    const int lanef = (oc & 7) * 4 + (klo >> 1);
    const int hsel = klo & 1;
    const int nt = oc >> 3, ntp = nt >> 1, ntl = nt & 1;
    const int frag = (((kh * 12 + ksq) * 4 + ntp) * 32 + lanef) * 8 + ntl * 4 + reg * 2 + hsel;
    const float b = w2b[row];
#pragma unroll
    for (int pi = 0; pi < 4; pi++) {
        float lo, hi;
        unpk2(acc2[pi], lo, hi);
        const int s0 = sg * 8 + 2 * pi;
        g_wB[(size_t)s0 * WFLAT + frag]       = __float2half_rn(lo + b);
        g_wB[(size_t)(s0 + 1) * WFLAT + frag] = __float2half_rn(hi + b);
    }
}

// ---------------------------------------------------------------------------
// convk: fp16 mma.sync implicit GEMM, kw fused into K (K=192 per kh).
// 128 px x 64 oc per CTA; A slab staged once; B double-buffered (24KB/kh).
// 6 barriers total (was 18). grid=(71,32), block=128.
// ---------------------------------------------------------------------------
#define ASTR 328                              // half2 units per icpair row
#define SMA_BYTES (32 * ASTR * 4)             // 41984
#define BKH 24576                             // bytes per kh B tile
#define SMEM_REQ  (SMA_BYTES + 2 * BKH)       // 91136

__global__ __launch_bounds__(128) void convk(const float* __restrict__ x,
                                             float* __restrict__ out) {
    extern __shared__ char S[];
    half2*  sA = (half2*)S;
    __half* sB = (__half*)(S + SMA_BYTES);
    const u32 sBu = smem_u32(S) + SMA_BYTES;

    const int tid  = threadIdx.x;
    const int lane = tid & 31, wrp = tid >> 5;
    const int s    = blockIdx.y;
    const int p0   = blockIdx.x * 128;
    const u32 xs0  = (u32)s * (64u * NPIX);
    const __half* gB0 = g_wB + (size_t)s * WFLAT;

    // ---- prefetch B kh=0 (rides under the A LDG burst): 1536 x 16B chunks ----
#pragma unroll
    for (int i = 0; i < 12; i++)
        cpa16(sBu + (u32)((i * 128 + tid) * 16), (const char*)gB0 + (i * 128 + tid) * 16);
    CPA_COMMIT();

    // ---- stage A: 32 icpairs x 322 px, fully unrolled (MLP ~24 LDG/thread) ----
#pragma unroll
    for (int ipl = 0; ipl < 8; ipl++) {
        const int ip  = wrp * 8 + ipl;
        const u32 r0b = xs0 + (u32)(2 * ip) * NPIX + (u32)p0;
#pragma unroll
        for (int c = 0; c < 3; c++) {
            const int px = c * 128 + lane * 4;
            u32 i0 = r0b + (u32)px;          if (i0 > XCLAMP) i0 = XCLAMP;
            u32 i1 = r0b + NPIX + (u32)px;   if (i1 > XCLAMP) i1 = XCLAMP;
            const float4 v0 = *(const float4*)(x + i0);
            const float4 v1 = *(const float4*)(x + i1);
            if (px < 326) {
                half2 h[4];
                h[0] = __floats2half2_rn(v0.x, v1.x);
                h[1] = __floats2half2_rn(v0.y, v1.y);
                h[2] = __floats2half2_rn(v0.z, v1.z);
                h[3] = __floats2half2_rn(v0.w, v1.w);
                *(uint4*)&sA[ip * ASTR + px] = *(const uint4*)h;
            }
        }
    }

    float acc[2][8][4];
#pragma unroll
    for (int mt = 0; mt < 2; mt++)
#pragma unroll
        for (int nt = 0; nt < 8; nt++)
#pragma unroll
            for (int r = 0; r < 4; r++) acc[mt][nt][r] = 0.f;

    const int pxb = wrp * 32 + (lane >> 2);

#pragma unroll 1
    for (int kh = 0; kh < 3; kh++) {
        if (kh < 2) {   // prefetch kh+1 into the other buffer
            const char* src = (const char*)gB0 + (size_t)(kh + 1) * BKH;
            const u32 dst = sBu + (u32)(((kh + 1) & 1) * BKH);
#pragma unroll
            for (int i = 0; i < 12; i++)
                cpa16(dst + (u32)((i * 128 + tid) * 16), src + (i * 128 + tid) * 16);
            CPA_COMMIT();
            CPA_WAIT(1);
        } else {
            CPA_WAIT(0);
        }
        __syncthreads();

        const __half* B = sB + (kh & 1) * (BKH / 2);
        const int offh = kh * 96;

#pragma unroll
        for (int ksq = 0; ksq < 12; ksq++) {
            const int kw = ksq >> 2, ks = ksq & 3;
            u32 b0[8], b1[8];
#pragma unroll
            for (int ntp = 0; ntp < 4; ntp++) {
                const uint4 bv = *(const uint4*)&B[((ksq * 4 + ntp) * 32 + lane) * 8];
                b0[2 * ntp + 0] = bv.x; b1[2 * ntp + 0] = bv.y;
                b0[2 * ntp + 1] = bv.z; b1[2 * ntp + 1] = bv.w;
            }
#pragma unroll
            for (int mt = 0; mt < 2; mt++) {
                const int a = (ks * 8 + (lane & 3)) * ASTR + pxb + mt * 16 + offh + kw;
                const u32 a0 = *(const u32*)&sA[a];
                const u32 a1 = *(const u32*)&sA[a + 8];
                const u32 a2 = *(const u32*)&sA[a + 4 * ASTR];
                const u32 a3 = *(const u32*)&sA[a + 4 * ASTR + 8];
#pragma unroll
                for (int nt = 0; nt < 8; nt++)
                    mma16(acc[mt][nt], a0, a1, a2, a3, b0[nt], b1[nt]);
            }
        }
        __syncthreads();
    }

    // ---- epilogue: D[px][oc]; mask h,w >= 94 ----
    const int oc0 = (lane & 3) * 2;
#pragma unroll
    for (int mt = 0; mt < 2; mt++) {
#pragma unroll
        for (int hf = 0; hf < 2; hf++) {
            const int px = p0 + pxb + mt * 16 + hf * 8;
            const int h = px / 96, w = px - h * 96;
            if (h < HOUT && w < HOUT) {
                float* op = out + ((size_t)s * 64) * 8836 + h * 94 + w;
#pragma unroll
                for (int nt = 0; nt < 8; nt++) {
                    op[(nt * 8 + oc0 + 0) * 8836] = acc[mt][nt][hf * 2 + 0];
                    op[(nt * 8 + oc0 + 1) * 8836] = acc[mt][nt][hf * 2 + 1];
                }
            }
        }
    }
}

// ---------------------------------------------------------------------------
extern "C" void kernel_launch(void* const* d_in, const int* in_sizes, int n_in,
                              void* d_out, int out_size) {
    const float* emb = (const float*)d_in[0];
    const float* x   = (const float*)d_in[1];
    const float* w1w = (const float*)d_in[2];
    const float* w1b = (const float*)d_in[3];
    const float* w2w = (const float*)d_in[4];
    const float* w2b = (const float*)d_in[5];
    float* out = (float*)d_out;

    cudaFuncSetAttribute(convk, cudaFuncAttributeMaxDynamicSharedMemorySize, SMEM_REQ);

    hyper1<<<128, 512>>>(emb, w1w, w1b);
    hyper2<<<WFLAT / 32, 128>>>(w2w, w2b);
    // tile 71 (px >= 9088) is entirely h >= 94 -> dropped
    convk<<<dim3(71, 32), 128, SMEM_REQ>>>(x, out);
}

// round 11
// speedup vs baseline: 1.2634x; 1.2634x over previous
#include <cuda_runtime.h>
#include <cuda_fp16.h>
#include <cstdint>

#define BS    32
#define EMB   512
#define GL    256
#define WFLAT 36864
#define HIN   96
#define HOUT  94
#define NPIX  9216
#define XCLAMP (32u*64u*9216u - 4u)

typedef unsigned long long u64;
typedef unsigned int u32;

// hdn in B-fragment order: [ks(16)][nt(4)][lane(32)][reg(2)][half(2)] fp16, 16KB
__device__ __align__(16) __half g_hdnF[8192];
// conv B fp16 fragment order: [s][kk][ks(4)][ntp(4)][lane(32)][ntl(2)][reg(2)][half(2)]
__device__ __align__(16) __half g_wB[BS * WFLAT];

// ---- helpers ----------------------------------------------------------------
__device__ __forceinline__ u32 smem_u32(const void* p) {
    u32 a; asm("{ .reg .u64 t; cvta.to.shared.u64 t, %1; cvt.u32.u64 %0, t; }" : "=r"(a) : "l"(p));
    return a;
}
__device__ __forceinline__ void cpa16(u32 dst, const void* src) {
    asm volatile("cp.async.cg.shared.global [%0], [%1], 16;" :: "r"(dst), "l"(src));
}
#define CPA_COMMIT() asm volatile("cp.async.commit_group;" ::: "memory")
#define CPA_WAIT(N)  asm volatile("cp.async.wait_group %0;" :: "n"(N) : "memory")

__device__ __forceinline__ void mma16(float* c, u32 a0, u32 a1, u32 a2, u32 a3,
                                      u32 b0, u32 b1) {
    asm("mma.sync.aligned.m16n8k16.row.col.f32.f16.f16.f32 "
        "{%0,%1,%2,%3}, {%4,%5,%6,%7}, {%8,%9}, {%0,%1,%2,%3};"
        : "+f"(c[0]), "+f"(c[1]), "+f"(c[2]), "+f"(c[3])
        : "r"(a0), "r"(a1), "r"(a2), "r"(a3), "r"(b0), "r"(b1));
}

// ---------------------------------------------------------------------------
// hyper1: hdn[j][s] = relu(emb[s,:]·w1[j,:] + b1[j]), written straight into
// the m16n8k16 B-fragment order (n=s, k=j) as fp16.
// grid = 128 (16 sample-pairs x 8 jg), block 512 = 32 j x 16 k-slices.
// ---------------------------------------------------------------------------
__global__ __launch_bounds__(512) void hyper1(const float* __restrict__ emb,
                                              const float* __restrict__ w1w,
                                              const float* __restrict__ w1b) {
    __shared__ float red[2][16][33];
    const int tid = threadIdx.x;
    const int sp = blockIdx.x >> 3, jg = blockIdx.x & 7;
    const int lane = tid & 31, slice = tid >> 5;
    const int j = jg * 32 + lane;
    const int s0 = sp * 2;
    const float4* wr = (const float4*)(w1w + (size_t)j * EMB + slice * 32);
    const float4* e0 = (const float4*)(emb + (size_t)s0 * EMB + slice * 32);
    const float4* e1 = (const float4*)(emb + (size_t)(s0 + 1) * EMB + slice * 32);
    float a0 = 0.f, a1 = 0.f;
#pragma unroll
    for (int k = 0; k < 8; k++) {
        const float4 w = wr[k];
        const float4 x0 = e0[k], x1 = e1[k];
        a0 += w.x * x0.x + w.y * x0.y + w.z * x0.z + w.w * x0.w;
        a1 += w.x * x1.x + w.y * x1.y + w.z * x1.z + w.w * x1.w;
    }
    red[0][slice][lane] = a0;
    red[1][slice][lane] = a1;
    __syncthreads();
    if (tid < 64) {
        const int si = tid >> 5, l = tid & 31;
        float a = 0.f;
#pragma unroll
        for (int t = 0; t < 16; t++) a += red[si][t][l];
        const int jj = jg * 32 + l;
        a += w1b[jj];
        a = a > 0.f ? a : 0.f;
        const int s = s0 + si;
        const int ks = jj >> 4, kpos = jj & 15;
        const int reg = kpos >> 3, klo = kpos & 7;
        const int lanef = (s & 7) * 4 + (klo >> 1);
        const int hsel = klo & 1;
        const int nt = s >> 3;
        g_hdnF[((ks * 4 + nt) * 32 + lanef) * 4 + reg * 2 + hsel] = __float2half_rn(a);
    }
}

// ---------------------------------------------------------------------------
// hyper2: weight GEMM on tensor cores. D[row, s] = w2[row,:]·hdn[:,s] + b2.
// CTA = 64 rows x 32 samples, block 128 (4 warps, 16 rows each).
// w2 staged per 64-k chunk as [kpair][m] half2 (stride 72, bank-bijective).
// hdn B-fragments cp.async'd once (16KB). Epilogue scatters fp16 into the
// conv B-fragment layout (identical to R9). grid = 576.
// ---------------------------------------------------------------------------
#define H2STR 72   // half2 units per kpair row (72 % 32 == 8 -> bijective banks)

__global__ __launch_bounds__(128) void hyper2(const float* __restrict__ w2w,
                                              const float* __restrict__ w2b) {
    __shared__ __align__(16) __half sH[8192];          // 16 KB hdn fragments
    __shared__ __align__(16) half2 sW[32 * H2STR];     // 9216 B w2 chunk

    const int tid = threadIdx.x;
    const int lane = tid & 31, wrp = tid >> 5;
    const int r0 = blockIdx.x * 64;

    // prefetch hdn fragments (1024 x 16B chunks / 128 thr = 8)
    const u32 sHu = smem_u32(sH);
#pragma unroll
    for (int i = 0; i < 8; i++)
        cpa16(sHu + (u32)((i * 128 + tid) * 16), (const char*)g_hdnF + (i * 128 + tid) * 16);
    CPA_COMMIT();

    float acc[4][4];
#pragma unroll
    for (int nt = 0; nt < 4; nt++)
#pragma unroll
        for (int r = 0; r < 4; r++) acc[nt][r] = 0.f;

    const int mbase = wrp * 16 + (lane >> 2);
    bool hwaited = false;

#pragma unroll 1
    for (int kc = 0; kc < 4; kc++) {
        __syncthreads();   // previous chunk consumed
        // stage chunk: 64 rows x 64 k -> sW[kp][m] half2=(k even, k odd)
#pragma unroll
        for (int it = 0; it < 8; it++) {
            const int idx = it * 128 + tid;     // 0..1023
            const int r = idx >> 4, k4 = idx & 15;
            const float4 v = *(const float4*)&w2w[(size_t)(r0 + r) * GL + kc * 64 + k4 * 4];
            sW[(2 * k4 + 0) * H2STR + r] = __floats2half2_rn(v.x, v.y);
            sW[(2 * k4 + 1) * H2STR + r] = __floats2half2_rn(v.z, v.w);
        }
        if (!hwaited) { CPA_WAIT(0); hwaited = true; }
        __syncthreads();

#pragma unroll
        for (int ks = 0; ks < 4; ks++) {
            const int ksg = kc * 4 + ks;
            const int ar = (ks * 8 + (lane & 3)) * H2STR + mbase;
            const u32 a0 = *(const u32*)&sW[ar];
            const u32 a1 = *(const u32*)&sW[ar + 8];
            const u32 a2 = *(const u32*)&sW[ar + 4 * H2STR];
            const u32 a3 = *(const u32*)&sW[ar + 4 * H2STR + 8];
#pragma unroll
            for (int nt = 0; nt < 4; nt++) {
                const uint2 bv = *(const uint2*)&sH[((ksg * 4 + nt) * 32 + lane) * 4];
                mma16(acc[nt], a0, a1, a2, a3, bv.x, bv.y);
            }
        }
    }

    // ---- epilogue: scatter into conv B-fragment layout ----
    const int row0 = r0 + wrp * 16 + (lane >> 2);
    const int row1 = row0 + 8;
    int  frg[2];
    float bias[2];
#pragma unroll
    for (int i = 0; i < 2; i++) {
        const int row = i ? row1 : row0;
        const int oc  = row / 576;
        const int rem = row - oc * 576;
        const int ic  = rem / 9;
        const int kk  = rem - ic * 9;
        const int ks = ic >> 4, kpos = ic & 15;
        const int reg = kpos >> 3, klo = kpos & 7;
        const int lanef = (oc & 7) * 4 + (klo >> 1);
        const int hsel = klo & 1;
        const int nt2 = oc >> 3, ntp = nt2 >> 1, ntl = nt2 & 1;
        frg[i] = (((kk * 4 + ks) * 4 + ntp) * 32 + lanef) * 8 + ntl * 4 + reg * 2 + hsel;
        bias[i] = w2b[row];
    }
#pragma unroll
    for (int nt = 0; nt < 4; nt++) {
        const int sA = nt * 8 + (lane & 3) * 2;
        g_wB[(size_t)(sA + 0) * WFLAT + frg[0]] = __float2half_rn(acc[nt][0] + bias[0]);
        g_wB[(size_t)(sA + 1) * WFLAT + frg[0]] = __float2half_rn(acc[nt][1] + bias[0]);
        g_wB[(size_t)(sA + 0) * WFLAT + frg[1]] = __float2half_rn(acc[nt][2] + bias[1]);
        g_wB[(size_t)(sA + 1) * WFLAT + frg[1]] = __float2half_rn(acc[nt][3] + bias[1]);
    }
}

// ---------------------------------------------------------------------------
// convk: R9 verbatim. fp16 mma.sync implicit GEMM. 128 px x 64 oc per CTA.
// A slab 32 icpairs x 322 px staged once; B double-buffered cp.async.
// B fragments loaded via LDS.128 (nt pairs). grid=(71,32), block=128.
// ---------------------------------------------------------------------------
#define ASTR 328                              // half2 units per icpair row
#define SMA_BYTES (32 * ASTR * 4)             // 41984
#define SMEM_REQ  (SMA_BYTES + 2 * 8192)      // 58368

__global__ __launch_bounds__(128) void convk(const float* __restrict__ x,
                                             float* __restrict__ out) {
    extern __shared__ char S[];
    half2*  sA = (half2*)S;
    __half* sB = (__half*)(S + SMA_BYTES);
    const u32 sBu = smem_u32(S) + SMA_BYTES;

    const int tid  = threadIdx.x;
    const int lane = tid & 31, wrp = tid >> 5;
    const int s    = blockIdx.y;
    const int p0   = blockIdx.x * 128;
    const u32 xs0  = (u32)s * (64u * NPIX);
    const __half* gB0 = g_wB + (size_t)s * WFLAT;

    // ---- prefetch B kk=0 (rides under the A LDG burst) ----
#pragma unroll
    for (int i = 0; i < 4; i++)
        cpa16(sBu + (u32)((i * 128 + tid) * 16), (const char*)gB0 + (i * 128 + tid) * 16);
    CPA_COMMIT();

    // ---- stage A: 32 icpairs x 322 px, fully unrolled (MLP ~24 LDG/thread) ----
#pragma unroll
    for (int ipl = 0; ipl < 8; ipl++) {
        const int ip  = wrp * 8 + ipl;
        const u32 r0b = xs0 + (u32)(2 * ip) * NPIX + (u32)p0;
#pragma unroll
        for (int c = 0; c < 3; c++) {
            const int px = c * 128 + lane * 4;
            u32 i0 = r0b + (u32)px;          if (i0 > XCLAMP) i0 = XCLAMP;
            u32 i1 = r0b + NPIX + (u32)px;   if (i1 > XCLAMP) i1 = XCLAMP;
            const float4 v0 = *(const float4*)(x + i0);
            const float4 v1 = *(const float4*)(x + i1);
            if (px < 326) {
                half2 h[4];
                h[0] = __floats2half2_rn(v0.x, v1.x);
                h[1] = __floats2half2_rn(v0.y, v1.y);
                h[2] = __floats2half2_rn(v0.z, v1.z);
                h[3] = __floats2half2_rn(v0.w, v1.w);
                *(uint4*)&sA[ip * ASTR + px] = *(const uint4*)h;
            }
        }
    }

    float acc[2][8][4];
#pragma unroll
    for (int mt = 0; mt < 2; mt++)
#pragma unroll
        for (int nt = 0; nt < 8; nt++)
#pragma unroll
            for (int r = 0; r < 4; r++) acc[mt][nt][r] = 0.f;

    const int pxb = wrp * 32 + (lane >> 2);

#pragma unroll 1
    for (int kk = 0; kk < 9; kk++) {
        if (kk < 8) {   // prefetch kk+1 into other buffer
            const char* src = (const char*)(gB0 + (size_t)(kk + 1) * 4096);
            const u32 dst = sBu + (u32)(((kk + 1) & 1) * 8192);
#pragma unroll
            for (int i = 0; i < 4; i++)
                cpa16(dst + (u32)((i * 128 + tid) * 16), src + (i * 128 + tid) * 16);
            CPA_COMMIT();
            CPA_WAIT(1);
        } else {
            CPA_WAIT(0);
        }
        __syncthreads();

        const int off = (kk / 3) * 96 + (kk % 3);
        const __half* B = sB + (kk & 1) * 4096;

#pragma unroll
        for (int ks = 0; ks < 4; ks++) {
            u32 b0[8], b1[8];
#pragma unroll
            for (int ntp = 0; ntp < 4; ntp++) {
                const uint4 bv = *(const uint4*)&B[((ks * 4 + ntp) * 32 + lane) * 8];
                b0[2 * ntp + 0] = bv.x; b1[2 * ntp + 0] = bv.y;
                b0[2 * ntp + 1] = bv.z; b1[2 * ntp + 1] = bv.w;
            }
#pragma unroll
            for (int mt = 0; mt < 2; mt++) {
                const int a = (ks * 8 + (lane & 3)) * ASTR + pxb + mt * 16 + off;
                const u32 a0 = *(const u32*)&sA[a];
                const u32 a1 = *(const u32*)&sA[a + 8];
                const u32 a2 = *(const u32*)&sA[a + 4 * ASTR];
                const u32 a3 = *(const u32*)&sA[a + 4 * ASTR + 8];
#pragma unroll
                for (int nt = 0; nt < 8; nt++)
                    mma16(acc[mt][nt], a0, a1, a2, a3, b0[nt], b1[nt]);
            }
        }
        __syncthreads();
    }

    // ---- epilogue: D[px][oc]; mask h,w >= 94 ----
    const int oc0 = (lane & 3) * 2;
#pragma unroll
    for (int mt = 0; mt < 2; mt++) {
#pragma unroll
        for (int hf = 0; hf < 2; hf++) {
            const int px = p0 + pxb + mt * 16 + hf * 8;
            const int h = px / 96, w = px - h * 96;
            if (h < HOUT && w < HOUT) {
                float* op = out + ((size_t)s * 64) * 8836 + h * 94 + w;
#pragma unroll
                for (int nt = 0; nt < 8; nt++) {
                    op[(nt * 8 + oc0 + 0) * 8836] = acc[mt][nt][hf * 2 + 0];
                    op[(nt * 8 + oc0 + 1) * 8836] = acc[mt][nt][hf * 2 + 1];
                }
            }
        }
    }
}

// ---------------------------------------------------------------------------
extern "C" void kernel_launch(void* const* d_in, const int* in_sizes, int n_in,
                              void* d_out, int out_size) {
    const float* emb = (const float*)d_in[0];
    const float* x   = (const float*)d_in[1];
    const float* w1w = (const float*)d_in[2];
    const float* w1b = (const float*)d_in[3];
    const float* w2w = (const float*)d_in[4];
    const float* w2b = (const float*)d_in[5];
    float* out = (float*)d_out;

    cudaFuncSetAttribute(convk, cudaFuncAttributeMaxDynamicSharedMemorySize, SMEM_REQ);

    hyper1<<<128, 512>>>(emb, w1w, w1b);
    hyper2<<<WFLAT / 64, 128>>>(w2w, w2b);
    // tile 71 (px >= 9088) is entirely h >= 94 -> dropped
    convk<<<dim3(71, 32), 128, SMEM_REQ>>>(x, out);
}